// round 3
// baseline (speedup 1.0000x reference)
#include <cuda_runtime.h>
#include <math.h>
#include <stdint.h>

// ---------------- static scratch (no allocations allowed) ----------------
#define MAXN 204800
#define MAXB 64
#define WMAX 128

__device__ int    g_warm_idx[MAXN];
__device__ int    g_cold_idx[MAXN];
__device__ int    g_nwarm;
__device__ int    g_ncold;
__device__ double g_kl_sum;
__device__ float  g_mu[(size_t)MAXN * WMAX];
__device__ float  g_lv[(size_t)MAXN * WMAX];
__device__ float  g_sim[(size_t)MAXB * MAXN];
__device__ float  g_qn[MAXB * 256];
__device__ float  g_invn[MAXN];
__device__ int    g_topidx[MAXB * 32];

__global__ void k_init() { g_nwarm = 0; g_ncold = 0; g_kl_sum = 0.0; }

__global__ void k_partition(const int* __restrict__ tiers, int N) {
    int i = blockIdx.x * blockDim.x + threadIdx.x;
    if (i >= N) return;
    int t = tiers[i];
    if (t == 1)      g_warm_idx[atomicAdd(&g_nwarm, 1)] = i;
    else if (t == 2) g_cold_idx[atomicAdd(&g_ncold, 1)] = i;
}

__global__ void k_copy4(const float4* __restrict__ src, float4* __restrict__ dst, long n4) {
    long i = (long)blockIdx.x * blockDim.x + threadIdx.x;
    if (i < n4) dst[i] = src[i];
}

__global__ __launch_bounds__(256) void k_qnorm(const float* __restrict__ q, int D) {
    int b = blockIdx.x, t = threadIdx.x;
    float ss = 0.f;
    for (int c = t; c < D; c += 256) { float v = q[(size_t)b * D + c]; ss += v * v; }
    __shared__ float red[256];
    red[t] = ss; __syncthreads();
    for (int s = 128; s > 0; s >>= 1) { if (t < s) red[t] += red[t + s]; __syncthreads(); }
    float scale = 1.f / (sqrtf(red[0]) + 1e-10f);
    for (int c = t; c < D; c += 256) g_qn[(size_t)b * D + c] = q[(size_t)b * D + c] * scale;
}

__global__ __launch_bounds__(256) void k_invnorm(const float* __restrict__ feats, int D) {
    int warp = threadIdx.x >> 5, lane = threadIdx.x & 31;
    int j = blockIdx.x * 8 + warp;
    if (j >= g_ncold) return;
    int row = g_cold_idx[j];
    const float* p = feats + (size_t)row * D;
    float ss = 0.f;
    for (int c = lane * 4; c < D; c += 128) {
        float4 v = *(const float4*)(p + c);
        ss += v.x * v.x + v.y * v.y + v.z * v.z + v.w * v.w;
    }
    #pragma unroll
    for (int o = 16; o > 0; o >>= 1) ss += __shfl_xor_sync(0xffffffffu, ss, o);
    if (lane == 0) g_invn[j] = 1.f / (sqrtf(ss) + 1e-10f);
}

// C[m][n] = sum_k A[row(m)][k] * Bm[n0+n][k] + bias[n0+n]
__global__ __launch_bounds__(256) void k_gemm(
    const float* __restrict__ A, int lda, int K,
    const float* __restrict__ Bm,
    const int* __restrict__ gidx,
    const int* __restrict__ Mcnt,
    float* __restrict__ C, int ldc,
    const int* __restrict__ sidx,
    const float* __restrict__ bias)
{
    const int M = *Mcnt;
    const int m0 = blockIdx.y * 128;
    if (m0 >= M) return;
    const int n0 = blockIdx.x * 128;

    __shared__ float As[16][128];
    __shared__ float Bs[16][128];

    const int tid = threadIdx.x;
    const int ty = tid >> 4, tx = tid & 15;

    float acc[8][8];
    #pragma unroll
    for (int i = 0; i < 8; i++)
        #pragma unroll
        for (int j = 0; j < 8; j++) acc[i][j] = 0.f;

    for (int k0 = 0; k0 < K; k0 += 16) {
        #pragma unroll
        for (int i = 0; i < 2; i++) {
            int id = tid + i * 256;
            int m = id & 127, kq = id >> 7;
            int r = m0 + m;
            int arow;
            if (gidx) arow = (r < M) ? gidx[r] : 0;
            else      arow = (r < M) ? r : 0;
            float4 v = *(const float4*)(A + (size_t)arow * lda + k0 + kq * 4);
            As[kq * 4 + 0][m] = v.x; As[kq * 4 + 1][m] = v.y;
            As[kq * 4 + 2][m] = v.z; As[kq * 4 + 3][m] = v.w;
        }
        #pragma unroll
        for (int i = 0; i < 2; i++) {
            int id = tid + i * 256;
            int n = id & 127, kq = id >> 7;
            float4 v = *(const float4*)(Bm + (size_t)(n0 + n) * K + k0 + kq * 4);
            Bs[kq * 4 + 0][n] = v.x; Bs[kq * 4 + 1][n] = v.y;
            Bs[kq * 4 + 2][n] = v.z; Bs[kq * 4 + 3][n] = v.w;
        }
        __syncthreads();
        #pragma unroll
        for (int kk = 0; kk < 16; kk++) {
            float4 a0 = *(const float4*)&As[kk][ty * 4];
            float4 a1 = *(const float4*)&As[kk][ty * 4 + 64];
            float4 b0 = *(const float4*)&Bs[kk][tx * 4];
            float4 b1 = *(const float4*)&Bs[kk][tx * 4 + 64];
            float a[8] = {a0.x, a0.y, a0.z, a0.w, a1.x, a1.y, a1.z, a1.w};
            float b[8] = {b0.x, b0.y, b0.z, b0.w, b1.x, b1.y, b1.z, b1.w};
            #pragma unroll
            for (int i = 0; i < 8; i++)
                #pragma unroll
                for (int j = 0; j < 8; j++) acc[i][j] += a[i] * b[j];
        }
        __syncthreads();
    }

    #pragma unroll
    for (int i = 0; i < 8; i++) {
        int rl = (i < 4) ? (ty * 4 + i) : (64 + ty * 4 + i - 4);
        int r = m0 + rl;
        if (r >= M) continue;
        int crow = sidx ? sidx[r] : r;
        #pragma unroll
        for (int j = 0; j < 8; j++) {
            int cl = (j < 4) ? (tx * 4 + j) : (64 + tx * 4 + j - 4);
            int c = n0 + cl;
            C[(size_t)crow * ldc + c] = acc[i][j] + (bias ? bias[c] : 0.f);
        }
    }
}

__global__ __launch_bounds__(256) void k_kl(int W) {
    long total = (long)g_nwarm * W;
    float s = 0.f;
    for (long i = (long)blockIdx.x * blockDim.x + threadIdx.x; i < total;
         i += (long)gridDim.x * blockDim.x) {
        float m = g_mu[i], l = g_lv[i];
        s += -0.5f * (1.f + l - m * m - expf(l));
    }
    __shared__ float red[256];
    int t = threadIdx.x;
    red[t] = s; __syncthreads();
    for (int o = 128; o > 0; o >>= 1) { if (t < o) red[t] += red[t + o]; __syncthreads(); }
    if (t == 0) atomicAdd(&g_kl_sum, (double)red[0]);
}

__global__ void k_klfin(float* klout, int W) {
    int n = g_nwarm > 0 ? g_nwarm : 1;
    *klout = (float)(g_kl_sum / ((double)n * (double)W));
}

__global__ __launch_bounds__(256) void k_sim(const float* __restrict__ feats, int D, int simld) {
    const int M = g_ncold;
    const int m0 = blockIdx.x * 128;
    if (m0 >= M) return;

    __shared__ float Xs[16][128];
    __shared__ float Qs[16][64];

    const int tid = threadIdx.x;
    const int ty = tid >> 4, tx = tid & 15;

    float acc[8][4];
    #pragma unroll
    for (int i = 0; i < 8; i++)
        #pragma unroll
        for (int j = 0; j < 4; j++) acc[i][j] = 0.f;

    for (int k0 = 0; k0 < D; k0 += 16) {
        #pragma unroll
        for (int i = 0; i < 2; i++) {
            int id = tid + i * 256;
            int m = id & 127, kq = id >> 7;
            int r = m0 + m;
            int arow = (r < M) ? g_cold_idx[r] : 0;
            float4 v = *(const float4*)(feats + (size_t)arow * D + k0 + kq * 4);
            Xs[kq * 4 + 0][m] = v.x; Xs[kq * 4 + 1][m] = v.y;
            Xs[kq * 4 + 2][m] = v.z; Xs[kq * 4 + 3][m] = v.w;
        }
        {
            int q = tid & 63, kq = tid >> 6;
            float4 v = *(const float4*)(g_qn + (size_t)q * D + k0 + kq * 4);
            Qs[kq * 4 + 0][q] = v.x; Qs[kq * 4 + 1][q] = v.y;
            Qs[kq * 4 + 2][q] = v.z; Qs[kq * 4 + 3][q] = v.w;
        }
        __syncthreads();
        #pragma unroll
        for (int kk = 0; kk < 16; kk++) {
            float4 a0 = *(const float4*)&Xs[kk][ty * 4];
            float4 a1 = *(const float4*)&Xs[kk][ty * 4 + 64];
            float4 b0 = *(const float4*)&Qs[kk][tx * 4];
            float a[8] = {a0.x, a0.y, a0.z, a0.w, a1.x, a1.y, a1.z, a1.w};
            float b[4] = {b0.x, b0.y, b0.z, b0.w};
            #pragma unroll
            for (int i = 0; i < 8; i++)
                #pragma unroll
                for (int j = 0; j < 4; j++) acc[i][j] += a[i] * b[j];
        }
        __syncthreads();
    }

    #pragma unroll
    for (int i = 0; i < 8; i++) {
        int rl = (i < 4) ? (ty * 4 + i) : (64 + ty * 4 + i - 4);
        int j = m0 + rl;
        if (j < M) {
            float inv = g_invn[j];
            #pragma unroll
            for (int jj = 0; jj < 4; jj++) {
                int q = tx * 4 + jj;
                g_sim[(size_t)q * simld + j] = acc[i][jj] * inv;
            }
        }
    }
}

__global__ __launch_bounds__(256) void k_topk(int simld, int k, float* __restrict__ out_idx_f) {
    const int b = blockIdx.x;
    const int ncold = g_ncold;
    const int t = threadIdx.x;

    float lv[16]; int li[16];
    #pragma unroll
    for (int s = 0; s < 16; s++) { lv[s] = -INFINITY; li[s] = 0x7fffffff; }

    const float* srow = g_sim + (size_t)b * simld;
    for (int j = t; j < ncold; j += 256) {
        float v = srow[j];
        int gi = g_cold_idx[j];
        if (v > lv[0] || (v == lv[0] && gi < li[0])) {
            lv[0] = v; li[0] = gi;
            #pragma unroll
            for (int s = 0; s < 15; s++) {
                bool sw = (lv[s] > lv[s + 1]) || (lv[s] == lv[s + 1] && li[s] < li[s + 1]);
                if (sw) {
                    float tv = lv[s]; lv[s] = lv[s + 1]; lv[s + 1] = tv;
                    int ti = li[s]; li[s] = li[s + 1]; li[s + 1] = ti;
                }
            }
        }
    }

    __shared__ float sval[4096];
    __shared__ int   sidxs[4096];
    __shared__ float rv[256];
    __shared__ int   ri[256];
    __shared__ int   rp[256];

    #pragma unroll
    for (int s = 0; s < 16; s++) { sval[t * 16 + s] = lv[s]; sidxs[t * 16 + s] = li[s]; }
    __syncthreads();

    for (int sel = 0; sel < k; sel++) {
        float bv = -INFINITY; int bi = 0x7fffffff; int bp = -1;
        for (int p = t; p < 4096; p += 256) {
            float v = sval[p]; int gi = sidxs[p];
            if (v > bv || (v == bv && gi < bi)) { bv = v; bi = gi; bp = p; }
        }
        rv[t] = bv; ri[t] = bi; rp[t] = bp;
        __syncthreads();
        for (int s = 128; s > 0; s >>= 1) {
            if (t < s) {
                if (rv[t + s] > rv[t] || (rv[t + s] == rv[t] && ri[t + s] < ri[t])) {
                    rv[t] = rv[t + s]; ri[t] = ri[t + s]; rp[t] = rp[t + s];
                }
            }
            __syncthreads();
        }
        if (t == 0) {
            g_topidx[b * 32 + sel] = ri[0];
            out_idx_f[(size_t)b * k + sel] = (float)ri[0];
            if (rp[0] >= 0) { sval[rp[0]] = -INFINITY; sidxs[rp[0]] = 0x7fffffff; }
        }
        __syncthreads();
    }
}

// Scalar copy: `ret` base is d_out + N*D + 1 floats -> only 4-byte aligned.
// float4 stores here caused the misaligned-address fault; D=256 floats/row is
// ~1 MB total so scalar stores cost <2 us.
__global__ __launch_bounds__(256) void k_gather(const float* __restrict__ newf,
                                                float* __restrict__ ret, int D, int k) {
    int r = blockIdx.x;
    int row = g_topidx[(r / k) * 32 + (r % k)];
    const float* s = newf + (size_t)row * D;
    float* d = ret + (size_t)r * D;
    for (int c = threadIdx.x; c < D; c += blockDim.x) d[c] = s[c];
}

extern "C" void kernel_launch(void* const* d_in, const int* in_sizes, int n_in,
                              void* d_out, int out_size) {
    const float* feats = (const float*)d_in[0];
    const int*   tiers = (const int*)d_in[1];
    const float* query = (const float*)d_in[2];
    const float* W_mu  = (const float*)d_in[3];
    const float* b_mu  = (const float*)d_in[4];
    const float* W_lv  = (const float*)d_in[5];
    const float* b_lv  = (const float*)d_in[6];
    const float* W_dec = (const float*)d_in[7];
    const float* b_dec = (const float*)d_in[8];

    const int N = in_sizes[1];
    const int D = in_sizes[0] / N;
    const int B = in_sizes[2] / D;
    const int W = in_sizes[4];
    const long k = ((long)out_size - (long)N * D - 1) / ((long)B * (D + 1));

    float* out   = (float*)d_out;
    float* newf  = out;
    float* klp   = out + (size_t)N * D;
    float* ret   = klp + 1;
    float* tidxf = ret + (size_t)B * k * D;

    void* pv;
    cudaGetSymbolAddress(&pv, g_nwarm);    int*   pnwarm = (int*)pv;
    cudaGetSymbolAddress(&pv, g_warm_idx); int*   pwarm  = (int*)pv;
    cudaGetSymbolAddress(&pv, g_mu);       float* pmu    = (float*)pv;
    cudaGetSymbolAddress(&pv, g_lv);       float* plv    = (float*)pv;

    k_init<<<1, 1>>>();
    k_partition<<<(N + 255) / 256, 256>>>(tiers, N);
    k_qnorm<<<B, 256>>>(query, D);
    k_invnorm<<<(N + 7) / 8, 256>>>(feats, D);

    long n4 = (long)N * D / 4;
    k_copy4<<<(unsigned)((n4 + 255) / 256), 256>>>((const float4*)feats, (float4*)newf, n4);

    const int gy = (N + 127) / 128;
    dim3 g1(1, gy);
    k_gemm<<<g1, 256>>>(feats, D, D, W_mu, pwarm, pnwarm, pmu, W, nullptr, b_mu);
    k_gemm<<<g1, 256>>>(feats, D, D, W_lv, pwarm, pnwarm, plv, W, nullptr, b_lv);

    k_kl<<<1024, 256>>>(W);
    k_klfin<<<1, 1>>>(klp, W);

    dim3 g2(D / 128, gy);
    k_gemm<<<g2, 256>>>(pmu, W, W, W_dec, nullptr, pnwarm, newf, D, pwarm, b_dec);

    k_sim<<<gy, 256>>>(feats, D, N);
    k_topk<<<B, 256>>>(N, (int)k, tidxf);
    k_gather<<<B * (int)k, 256>>>(newf, ret, D, (int)k);
}

// round 5
// speedup vs baseline: 1.4166x; 1.4166x over previous
#include <cuda_runtime.h>
#include <cuda_bf16.h>
#include <math.h>
#include <stdint.h>

// ---------------- static scratch (no allocations allowed) ----------------
#define MAXN 204800
#define MAXB 64

__device__ int    g_warm_idx[MAXN];
__device__ int    g_cold_idx[MAXN];
__device__ int    g_nwarm;
__device__ int    g_ncold;
__device__ double g_kl_sum;
__device__ float  g_sim[(size_t)MAXB * MAXN];
__device__ float  g_qn[MAXB * 256];
__device__ int    g_topidx[MAXB * 32];
__device__ __nv_bfloat16 g_muh[(size_t)MAXN * 128];  // mu hi (bf16), warm-compacted
__device__ __nv_bfloat16 g_mul[(size_t)MAXN * 128];  // mu lo (bf16)

// ---------------- helpers ----------------
__device__ __forceinline__ uint32_t pk2(__nv_bfloat16 a, __nv_bfloat16 b) {
    return (uint32_t)__bfloat16_as_ushort(a) | ((uint32_t)__bfloat16_as_ushort(b) << 16);
}

// mma.sync m16n8k16 row.col f32.bf16.bf16.f32 (sm_80+, compiles for compute_103)
#define MMA16816(c, a, b) asm volatile( \
    "mma.sync.aligned.m16n8k16.row.col.f32.bf16.bf16.f32 " \
    "{%0,%1,%2,%3}, {%4,%5,%6,%7}, {%8,%9}, {%0,%1,%2,%3};" \
    : "+f"((c)[0]), "+f"((c)[1]), "+f"((c)[2]), "+f"((c)[3]) \
    : "r"((a)[0]), "r"((a)[1]), "r"((a)[2]), "r"((a)[3]), "r"((b)[0]), "r"((b)[1]))

// dynamic smem: 4 tiles of [128][72] bf16 (stride 72 = conflict-free frags)
#define TSTRIDE 72
#define TBYTES  (128 * TSTRIDE * 2)   // 18432
#define OFF_AH  0
#define OFF_AL  (TBYTES)
#define OFF_BH  (2 * TBYTES)
#define OFF_BL  (3 * TBYTES)
#define DSMEM_SZ (4 * TBYTES)         // 73728

// split fp32x4 -> bf16 hi/lo, store 8B each into [m][k..k+3] of hi/lo tiles
__device__ __forceinline__ void split_store4(char* smem, int m, int k, float4 v,
                                             int off_hi, int off_lo) {
    __nv_bfloat16 h0 = __float2bfloat16(v.x), h1 = __float2bfloat16(v.y);
    __nv_bfloat16 h2 = __float2bfloat16(v.z), h3 = __float2bfloat16(v.w);
    float l0 = v.x - __bfloat162float(h0), l1 = v.y - __bfloat162float(h1);
    float l2 = v.z - __bfloat162float(h2), l3 = v.w - __bfloat162float(h3);
    size_t base = (size_t)m * TSTRIDE + k;
    *(uint2*)(smem + off_hi + base * 2) = make_uint2(pk2(h0, h1), pk2(h2, h3));
    *(uint2*)(smem + off_lo + base * 2) =
        make_uint2(pk2(__float2bfloat16(l0), __float2bfloat16(l1)),
                   pk2(__float2bfloat16(l2), __float2bfloat16(l3)));
}

// load A-fragment (m16k16) regs from padded smem tile
__device__ __forceinline__ void ldfragA(const char* smem, int off, int r, int kk,
                                        int lane, uint32_t a[4]) {
    const __nv_bfloat16* T = (const __nv_bfloat16*)(smem + off);
    int g = lane >> 2, q = (lane & 3) * 2;
    a[0] = *(const uint32_t*)&T[(size_t)(r + g)     * TSTRIDE + kk + q];
    a[1] = *(const uint32_t*)&T[(size_t)(r + g + 8) * TSTRIDE + kk + q];
    a[2] = *(const uint32_t*)&T[(size_t)(r + g)     * TSTRIDE + kk + q + 8];
    a[3] = *(const uint32_t*)&T[(size_t)(r + g + 8) * TSTRIDE + kk + q + 8];
}
// load B-fragment (k16n8) regs; smem tile stores B as [n][k]
__device__ __forceinline__ void ldfragB(const char* smem, int off, int n, int kk,
                                        int lane, uint32_t b[2]) {
    const __nv_bfloat16* T = (const __nv_bfloat16*)(smem + off);
    int g = lane >> 2, q = (lane & 3) * 2;
    b[0] = *(const uint32_t*)&T[(size_t)(n + g) * TSTRIDE + kk + q];
    b[1] = *(const uint32_t*)&T[(size_t)(n + g) * TSTRIDE + kk + q + 8];
}

// ---------------- small kernels ----------------
__global__ void k_init() { g_nwarm = 0; g_ncold = 0; g_kl_sum = 0.0; }

__global__ void k_partition(const int* __restrict__ tiers, int N) {
    int i = blockIdx.x * blockDim.x + threadIdx.x;
    if (i >= N) return;
    int t = tiers[i];
    if (t == 1)      g_warm_idx[atomicAdd(&g_nwarm, 1)] = i;
    else if (t == 2) g_cold_idx[atomicAdd(&g_ncold, 1)] = i;
}

// copy new_features = node_features, skipping warm rows (dec overwrites them)
__global__ void k_copy4(const float4* __restrict__ src, float4* __restrict__ dst,
                        const int* __restrict__ tiers, long n4) {
    long i = (long)blockIdx.x * blockDim.x + threadIdx.x;
    if (i >= n4) return;
    int row = (int)(i >> 6);  // 64 float4 per 256-float row
    if (tiers[row] != 1) dst[i] = src[i];
}

__global__ __launch_bounds__(256) void k_qnorm(const float* __restrict__ q, int D) {
    int b = blockIdx.x, t = threadIdx.x;
    float ss = 0.f;
    for (int c = t; c < D; c += 256) { float v = q[(size_t)b * D + c]; ss += v * v; }
    __shared__ float red[256];
    red[t] = ss; __syncthreads();
    for (int s = 128; s > 0; s >>= 1) { if (t < s) red[t] += red[t + s]; __syncthreads(); }
    float scale = 1.f / (sqrtf(red[0]) + 1e-10f);
    for (int c = t; c < D; c += 256) g_qn[(size_t)b * D + c] = q[(size_t)b * D + c] * scale;
}

__global__ void k_klfin(float* klout, int W) {
    int n = g_nwarm > 0 ? g_nwarm : 1;
    *klout = (float)(g_kl_sum / ((double)n * (double)W));
}

// ---------------- VAE encoder (HMMA): out = X_warm @ Wsel^T ----------------
// grid (gy, 2): by=0 -> mu (split-store + KL mu-part), by=1 -> lv (KL lv-part)
// Block tile 128x128, K=256 in 4 chunks of 64. 3-pass hi/lo split.
__global__ __launch_bounds__(512)
void k_vae(const float* __restrict__ feats,
           const float* __restrict__ W_mu, const float* __restrict__ b_mu,
           const float* __restrict__ W_lv, const float* __restrict__ b_lv) {
    extern __shared__ char smem[];
    const int M = g_nwarm;
    const int m0 = blockIdx.x * 128;
    if (m0 >= M) return;
    const int is_lv = blockIdx.y;
    const float* Wsel = is_lv ? W_lv : W_mu;
    const float* bsel = is_lv ? b_lv : b_mu;

    const int tid = threadIdx.x, wid = tid >> 5, lane = tid & 31;
    const int wm = wid >> 2, wn = wid & 3;  // 4x4 warp grid, 32x32 warp tile

    float acc[2][4][4];
    #pragma unroll
    for (int mi = 0; mi < 2; mi++)
        #pragma unroll
        for (int ni = 0; ni < 4; ni++)
            #pragma unroll
            for (int j = 0; j < 4; j++) acc[mi][ni][j] = 0.f;

    for (int k0 = 0; k0 < 256; k0 += 64) {
        // stage A: 128 warm rows x 64 cols fp32 -> split bf16
        #pragma unroll
        for (int it = 0; it < 4; it++) {
            int id = tid + it * 512;           // 2048 float4 total
            int m = id >> 4, kq = id & 15;
            int r = m0 + m;
            int arow = g_warm_idx[(r < M) ? r : m0];
            float4 v = *(const float4*)(feats + (size_t)arow * 256 + k0 + kq * 4);
            split_store4(smem, m, kq * 4, v, OFF_AH, OFF_AL);
        }
        // stage B: Wsel rows 0..127 x 64 cols
        #pragma unroll
        for (int it = 0; it < 4; it++) {
            int id = tid + it * 512;
            int n = id >> 4, kq = id & 15;
            float4 v = *(const float4*)(Wsel + (size_t)n * 256 + k0 + kq * 4);
            split_store4(smem, n, kq * 4, v, OFF_BH, OFF_BL);
        }
        __syncthreads();

        #pragma unroll
        for (int kk = 0; kk < 64; kk += 16) {
            uint32_t ah[2][4], al[2][4], bh[4][2], bl[4][2];
            #pragma unroll
            for (int mi = 0; mi < 2; mi++) {
                int r = wm * 32 + mi * 16;
                ldfragA(smem, OFF_AH, r, kk, lane, ah[mi]);
                ldfragA(smem, OFF_AL, r, kk, lane, al[mi]);
            }
            #pragma unroll
            for (int ni = 0; ni < 4; ni++) {
                int n = wn * 32 + ni * 8;
                ldfragB(smem, OFF_BH, n, kk, lane, bh[ni]);
                ldfragB(smem, OFF_BL, n, kk, lane, bl[ni]);
            }
            #pragma unroll
            for (int mi = 0; mi < 2; mi++)
                #pragma unroll
                for (int ni = 0; ni < 4; ni++) {
                    MMA16816(acc[mi][ni], ah[mi], bh[ni]);
                    MMA16816(acc[mi][ni], ah[mi], bl[ni]);
                    MMA16816(acc[mi][ni], al[mi], bh[ni]);
                }
        }
        __syncthreads();
    }

    // epilogue
    const int gq = lane >> 2, qq = (lane & 3) * 2;
    float kl = 0.f;
    #pragma unroll
    for (int mi = 0; mi < 2; mi++) {
        #pragma unroll
        for (int half = 0; half < 2; half++) {
            int rl = wm * 32 + mi * 16 + gq + half * 8;
            int grow = m0 + rl;
            if (grow >= M) continue;
            #pragma unroll
            for (int ni = 0; ni < 4; ni++) {
                int col = wn * 32 + ni * 8 + qq;
                float v0 = acc[mi][ni][half * 2 + 0] + bsel[col];
                float v1 = acc[mi][ni][half * 2 + 1] + bsel[col + 1];
                if (!is_lv) {
                    // mu: split-store for decoder + KL mu-part
                    __nv_bfloat16 h0 = __float2bfloat16(v0), h1 = __float2bfloat16(v1);
                    float l0 = v0 - __bfloat162float(h0), l1 = v1 - __bfloat162float(h1);
                    size_t o = (size_t)grow * 128 + col;
                    *(uint32_t*)(g_muh + o) = pk2(h0, h1);
                    *(uint32_t*)(g_mul + o) = pk2(__float2bfloat16(l0), __float2bfloat16(l1));
                    kl += 0.5f * (v0 * v0 + v1 * v1) - 1.0f;
                } else {
                    kl += 0.5f * (expf(v0) + expf(v1)) - 0.5f * (v0 + v1);
                }
            }
        }
    }
    #pragma unroll
    for (int o = 16; o > 0; o >>= 1) kl += __shfl_xor_sync(0xffffffffu, kl, o);
    if (lane == 0 && kl != 0.f) atomicAdd(&g_kl_sum, (double)kl);
}

// ---------------- decoder (HMMA): dec = mu @ W_dec^T + b_dec ----------------
// grid (gy, 2): n0 = by*128 selects output col half. A already split bf16.
__global__ __launch_bounds__(512)
void k_dec(const float* __restrict__ W_dec, const float* __restrict__ b_dec,
           float* __restrict__ newf) {
    extern __shared__ char smem[];
    const int M = g_nwarm;
    const int m0 = blockIdx.x * 128;
    if (m0 >= M) return;
    const int n0 = blockIdx.y * 128;

    const int tid = threadIdx.x, wid = tid >> 5, lane = tid & 31;
    const int wm = wid >> 2, wn = wid & 3;

    float acc[2][4][4];
    #pragma unroll
    for (int mi = 0; mi < 2; mi++)
        #pragma unroll
        for (int ni = 0; ni < 4; ni++)
            #pragma unroll
            for (int j = 0; j < 4; j++) acc[mi][ni][j] = 0.f;

    for (int k0 = 0; k0 < 128; k0 += 64) {
        // stage A: copy split-bf16 mu (hi/lo), 128 rows x 64 cols
        #pragma unroll
        for (int it = 0; it < 2; it++) {
            int id = tid + it * 512;           // 1024 uint4 per tile
            int m = id >> 3, q = id & 7;       // q: 8 bf16 chunks
            int r = m0 + m;
            size_t src = (size_t)((r < M) ? r : m0) * 128 + k0 + q * 8;
            size_t dst = ((size_t)m * TSTRIDE + q * 8) * 2;
            *(uint4*)(smem + OFF_AH + dst) = *(const uint4*)(g_muh + src);
            *(uint4*)(smem + OFF_AL + dst) = *(const uint4*)(g_mul + src);
        }
        // stage B: W_dec rows n0..n0+127 x 64 cols fp32 -> split
        #pragma unroll
        for (int it = 0; it < 4; it++) {
            int id = tid + it * 512;
            int n = id >> 4, kq = id & 15;
            float4 v = *(const float4*)(W_dec + (size_t)(n0 + n) * 128 + k0 + kq * 4);
            split_store4(smem, n, kq * 4, v, OFF_BH, OFF_BL);
        }
        __syncthreads();

        #pragma unroll
        for (int kk = 0; kk < 64; kk += 16) {
            uint32_t ah[2][4], al[2][4], bh[4][2], bl[4][2];
            #pragma unroll
            for (int mi = 0; mi < 2; mi++) {
                int r = wm * 32 + mi * 16;
                ldfragA(smem, OFF_AH, r, kk, lane, ah[mi]);
                ldfragA(smem, OFF_AL, r, kk, lane, al[mi]);
            }
            #pragma unroll
            for (int ni = 0; ni < 4; ni++) {
                int n = wn * 32 + ni * 8;
                ldfragB(smem, OFF_BH, n, kk, lane, bh[ni]);
                ldfragB(smem, OFF_BL, n, kk, lane, bl[ni]);
            }
            #pragma unroll
            for (int mi = 0; mi < 2; mi++)
                #pragma unroll
                for (int ni = 0; ni < 4; ni++) {
                    MMA16816(acc[mi][ni], ah[mi], bh[ni]);
                    MMA16816(acc[mi][ni], ah[mi], bl[ni]);
                    MMA16816(acc[mi][ni], al[mi], bh[ni]);
                }
        }
        __syncthreads();
    }

    // epilogue: scatter into new_features at warm rows
    const int gq = lane >> 2, qq = (lane & 3) * 2;
    #pragma unroll
    for (int mi = 0; mi < 2; mi++) {
        #pragma unroll
        for (int half = 0; half < 2; half++) {
            int rl = wm * 32 + mi * 16 + gq + half * 8;
            int grow = m0 + rl;
            if (grow >= M) continue;
            int wr = g_warm_idx[grow];
            #pragma unroll
            for (int ni = 0; ni < 4; ni++) {
                int col = n0 + wn * 32 + ni * 8 + qq;
                float2 v = make_float2(acc[mi][ni][half * 2 + 0] + b_dec[col],
                                       acc[mi][ni][half * 2 + 1] + b_dec[col + 1]);
                *(float2*)(newf + (size_t)wr * 256 + col) = v;
            }
        }
    }
}

// ---------------- sim GEMM (fp32 SIMT; fused row norms) -------------------
__global__ __launch_bounds__(256) void k_sim(const float* __restrict__ feats, int D, int simld) {
    const int M = g_ncold;
    const int m0 = blockIdx.x * 128;
    if (m0 >= M) return;

    __shared__ float Xs[16][128];
    __shared__ float Qs[16][64];

    const int tid = threadIdx.x;
    const int ty = tid >> 4, tx = tid & 15;

    float acc[8][4];
    float ssq[8];
    #pragma unroll
    for (int i = 0; i < 8; i++) {
        ssq[i] = 0.f;
        #pragma unroll
        for (int j = 0; j < 4; j++) acc[i][j] = 0.f;
    }

    for (int k0 = 0; k0 < D; k0 += 16) {
        #pragma unroll
        for (int i = 0; i < 2; i++) {
            int id = tid + i * 256;
            int m = id & 127, kq = id >> 7;
            int r = m0 + m;
            int arow = (r < M) ? g_cold_idx[r] : g_cold_idx[m0];
            float4 v = *(const float4*)(feats + (size_t)arow * D + k0 + kq * 4);
            Xs[kq * 4 + 0][m] = v.x; Xs[kq * 4 + 1][m] = v.y;
            Xs[kq * 4 + 2][m] = v.z; Xs[kq * 4 + 3][m] = v.w;
        }
        {
            int q = tid & 63, kq = tid >> 6;
            float4 v = *(const float4*)(g_qn + (size_t)q * D + k0 + kq * 4);
            Qs[kq * 4 + 0][q] = v.x; Qs[kq * 4 + 1][q] = v.y;
            Qs[kq * 4 + 2][q] = v.z; Qs[kq * 4 + 3][q] = v.w;
        }
        __syncthreads();
        #pragma unroll
        for (int kk = 0; kk < 16; kk++) {
            float4 a0 = *(const float4*)&Xs[kk][ty * 4];
            float4 a1 = *(const float4*)&Xs[kk][ty * 4 + 64];
            float4 b0 = *(const float4*)&Qs[kk][tx * 4];
            float a[8] = {a0.x, a0.y, a0.z, a0.w, a1.x, a1.y, a1.z, a1.w};
            float b[4] = {b0.x, b0.y, b0.z, b0.w};
            #pragma unroll
            for (int i = 0; i < 8; i++) {
                ssq[i] += a[i] * a[i];
                #pragma unroll
                for (int j = 0; j < 4; j++) acc[i][j] += a[i] * b[j];
            }
        }
        __syncthreads();
    }

    #pragma unroll
    for (int i = 0; i < 8; i++) {
        int rl = (i < 4) ? (ty * 4 + i) : (64 + ty * 4 + i - 4);
        int j = m0 + rl;
        if (j < M) {
            float inv = 1.f / (sqrtf(ssq[i]) + 1e-10f);
            #pragma unroll
            for (int jj = 0; jj < 4; jj++) {
                int q = tx * 4 + jj;
                g_sim[(size_t)q * simld + j] = acc[i][jj] * inv;
            }
        }
    }
}

// ---------------- top-k (value desc, index asc tie-break) ------------------
__global__ __launch_bounds__(256) void k_topk(int simld, int k, float* __restrict__ out_idx_f) {
    const int b = blockIdx.x;
    const int ncold = g_ncold;
    const int t = threadIdx.x;

    float lv[16]; int li[16];
    #pragma unroll
    for (int s = 0; s < 16; s++) { lv[s] = -INFINITY; li[s] = 0x7fffffff; }

    const float* srow = g_sim + (size_t)b * simld;
    for (int j = t; j < ncold; j += 256) {
        float v = srow[j];
        int gi = g_cold_idx[j];
        if (v > lv[0] || (v == lv[0] && gi < li[0])) {
            lv[0] = v; li[0] = gi;
            #pragma unroll
            for (int s = 0; s < 15; s++) {
                bool sw = (lv[s] > lv[s + 1]) || (lv[s] == lv[s + 1] && li[s] < li[s + 1]);
                if (sw) {
                    float tv = lv[s]; lv[s] = lv[s + 1]; lv[s + 1] = tv;
                    int ti = li[s]; li[s] = li[s + 1]; li[s + 1] = ti;
                }
            }
        }
    }

    __shared__ float sval[4096];
    __shared__ int   sidxs[4096];
    __shared__ float rv[256];
    __shared__ int   ri[256];
    __shared__ int   rp[256];

    #pragma unroll
    for (int s = 0; s < 16; s++) { sval[t * 16 + s] = lv[s]; sidxs[t * 16 + s] = li[s]; }
    __syncthreads();

    for (int sel = 0; sel < k; sel++) {
        float bv = -INFINITY; int bi = 0x7fffffff; int bp = -1;
        for (int p = t; p < 4096; p += 256) {
            float v = sval[p]; int gi = sidxs[p];
            if (v > bv || (v == bv && gi < bi)) { bv = v; bi = gi; bp = p; }
        }
        rv[t] = bv; ri[t] = bi; rp[t] = bp;
        __syncthreads();
        for (int s = 128; s > 0; s >>= 1) {
            if (t < s) {
                if (rv[t + s] > rv[t] || (rv[t + s] == rv[t] && ri[t + s] < ri[t])) {
                    rv[t] = rv[t + s]; ri[t] = ri[t + s]; rp[t] = rp[t + s];
                }
            }
            __syncthreads();
        }
        if (t == 0) {
            g_topidx[b * 32 + sel] = ri[0];
            out_idx_f[(size_t)b * k + sel] = (float)ri[0];
            if (rp[0] >= 0) { sval[rp[0]] = -INFINITY; sidxs[rp[0]] = 0x7fffffff; }
        }
        __syncthreads();
    }
}

// Scalar stores: ret base is d_out + N*D + 1 floats (only 4B aligned).
__global__ __launch_bounds__(256) void k_gather(const float* __restrict__ newf,
                                                float* __restrict__ ret, int D, int k) {
    int r = blockIdx.x;
    int row = g_topidx[(r / k) * 32 + (r % k)];
    const float* s = newf + (size_t)row * D;
    float* d = ret + (size_t)r * D;
    for (int c = threadIdx.x; c < D; c += blockDim.x) d[c] = s[c];
}

extern "C" void kernel_launch(void* const* d_in, const int* in_sizes, int n_in,
                              void* d_out, int out_size) {
    const float* feats = (const float*)d_in[0];
    const int*   tiers = (const int*)d_in[1];
    const float* query = (const float*)d_in[2];
    const float* W_mu  = (const float*)d_in[3];
    const float* b_mu  = (const float*)d_in[4];
    const float* W_lv  = (const float*)d_in[5];
    const float* b_lv  = (const float*)d_in[6];
    const float* W_dec = (const float*)d_in[7];
    const float* b_dec = (const float*)d_in[8];

    const int N = in_sizes[1];
    const int D = in_sizes[0] / N;
    const int B = in_sizes[2] / D;
    const int W = in_sizes[4];
    const long k = ((long)out_size - (long)N * D - 1) / ((long)B * (D + 1));

    float* out   = (float*)d_out;
    float* newf  = out;
    float* klp   = out + (size_t)N * D;
    float* ret   = klp + 1;
    float* tidxf = ret + (size_t)B * k * D;

    cudaFuncSetAttribute(k_vae, cudaFuncAttributeMaxDynamicSharedMemorySize, DSMEM_SZ);
    cudaFuncSetAttribute(k_dec, cudaFuncAttributeMaxDynamicSharedMemorySize, DSMEM_SZ);

    k_init<<<1, 1>>>();
    k_partition<<<(N + 255) / 256, 256>>>(tiers, N);
    k_qnorm<<<B, 256>>>(query, D);

    long n4 = (long)N * D / 4;
    k_copy4<<<(unsigned)((n4 + 255) / 256), 256>>>((const float4*)feats, (float4*)newf, tiers, n4);

    const int gy = (N + 127) / 128;
    k_vae<<<dim3(gy, 2), 512, DSMEM_SZ>>>(feats, W_mu, b_mu, W_lv, b_lv);
    k_klfin<<<1, 1>>>(klp, W);
    k_dec<<<dim3(gy, 2), 512, DSMEM_SZ>>>(W_dec, b_dec, newf);

    k_sim<<<gy, 256>>>(feats, D, N);
    k_topk<<<B, 256>>>(N, (int)k, tidxf);
    k_gather<<<B * (int)k, 256>>>(newf, ret, D, (int)k);
}

// round 6
// speedup vs baseline: 1.4748x; 1.0411x over previous
#include <cuda_runtime.h>
#include <cuda_bf16.h>
#include <math.h>
#include <stdint.h>

// ---------------- static scratch (no allocations allowed) ----------------
#define MAXN 204800
#define MAXB 64

__device__ int    g_warm_idx[MAXN];
__device__ int    g_cold_idx[MAXN];
__device__ int    g_nwarm;
__device__ int    g_ncold;
__device__ double g_kl_sum;
__device__ float  g_sim[(size_t)MAXB * MAXN];
__device__ float  g_qn[MAXB * 256];
__device__ int    g_topidx[MAXB * 32];
__device__ __nv_bfloat16 g_muh[(size_t)MAXN * 128];   // mu hi (bf16), warm-compacted
__device__ __nv_bfloat16 g_mul[(size_t)MAXN * 128];   // mu lo (bf16)
// pre-converted weights (hi/lo split), [n][k] row-major
__device__ __nv_bfloat16 g_Wh[256 * 256];  // rows 0-127 = W_mu, 128-255 = W_lv
__device__ __nv_bfloat16 g_Wl[256 * 256];
__device__ __nv_bfloat16 g_Dh[256 * 128];  // W_dec
__device__ __nv_bfloat16 g_Dl[256 * 128];

// ---------------- helpers ----------------
__device__ __forceinline__ uint32_t pk2(__nv_bfloat16 a, __nv_bfloat16 b) {
    return (uint32_t)__bfloat16_as_ushort(a) | ((uint32_t)__bfloat16_as_ushort(b) << 16);
}
__device__ __forceinline__ uint32_t smem_u32(const void* p) {
    uint32_t a;
    asm("{ .reg .u64 t; cvta.to.shared.u64 t, %1; cvt.u32.u64 %0, t; }" : "=r"(a) : "l"(p));
    return a;
}

#define MMA16816(c, a, b) asm volatile( \
    "mma.sync.aligned.m16n8k16.row.col.f32.bf16.bf16.f32 " \
    "{%0,%1,%2,%3}, {%4,%5,%6,%7}, {%8,%9}, {%0,%1,%2,%3};" \
    : "+f"((c)[0]), "+f"((c)[1]), "+f"((c)[2]), "+f"((c)[3]) \
    : "r"((a)[0]), "r"((a)[1]), "r"((a)[2]), "r"((a)[3]), "r"((b)[0]), "r"((b)[1]))

__device__ __forceinline__ void ldm4(uint32_t addr, uint32_t r[4]) {
    asm volatile("ldmatrix.sync.aligned.m8n8.x4.shared.b16 {%0,%1,%2,%3}, [%4];"
                 : "=r"(r[0]), "=r"(r[1]), "=r"(r[2]), "=r"(r[3]) : "r"(addr));
}

// padded smem tiles: stride 72 bf16 (144B) -> conflict-free ldmatrix
#define TSTRIDE 72
#define OFF_AH 0
#define OFF_AL 18432
#define OFF_BH 36864
#define OFF_BL 73728
#define DSMEM_SZ 110592

// split fp32x4 -> bf16 hi/lo, store 8B each into [m][k..k+3]
__device__ __forceinline__ void split_store4(char* smem, int m, int k, float4 v,
                                             int off_hi, int off_lo) {
    __nv_bfloat16 h0 = __float2bfloat16(v.x), h1 = __float2bfloat16(v.y);
    __nv_bfloat16 h2 = __float2bfloat16(v.z), h3 = __float2bfloat16(v.w);
    float l0 = v.x - __bfloat162float(h0), l1 = v.y - __bfloat162float(h1);
    float l2 = v.z - __bfloat162float(h2), l3 = v.w - __bfloat162float(h3);
    size_t base = (size_t)m * TSTRIDE + k;
    *(uint2*)(smem + off_hi + base * 2) = make_uint2(pk2(h0, h1), pk2(h2, h3));
    *(uint2*)(smem + off_lo + base * 2) =
        make_uint2(pk2(__float2bfloat16(l0), __float2bfloat16(l1)),
                   pk2(__float2bfloat16(l2), __float2bfloat16(l3)));
}

// ---------------- small kernels ----------------
__global__ void k_init() { g_nwarm = 0; g_ncold = 0; g_kl_sum = 0.0; }

__global__ void k_partition(const int* __restrict__ tiers, int N) {
    int i = blockIdx.x * blockDim.x + threadIdx.x;
    if (i >= N) return;
    int t = tiers[i];
    if (t == 1)      g_warm_idx[atomicAdd(&g_nwarm, 1)] = i;
    else if (t == 2) g_cold_idx[atomicAdd(&g_ncold, 1)] = i;
}

// pre-convert weights to split bf16 (runs once per launch, ~100K elems)
__global__ __launch_bounds__(256) void k_wprep(const float* __restrict__ W_mu,
                                               const float* __restrict__ W_lv,
                                               const float* __restrict__ W_dec) {
    int idx = blockIdx.x * blockDim.x + threadIdx.x;
    if (idx < 65536) {
        int n = idx >> 8, k = idx & 255;
        float w = (n < 128) ? W_mu[(size_t)n * 256 + k] : W_lv[(size_t)(n - 128) * 256 + k];
        __nv_bfloat16 h = __float2bfloat16(w);
        g_Wh[idx] = h;
        g_Wl[idx] = __float2bfloat16(w - __bfloat162float(h));
    } else if (idx < 65536 + 32768) {
        int j = idx - 65536;
        float w = W_dec[j];
        __nv_bfloat16 h = __float2bfloat16(w);
        g_Dh[j] = h;
        g_Dl[j] = __float2bfloat16(w - __bfloat162float(h));
    }
}

// copy new_features = node_features, skipping warm rows (dec overwrites them)
__global__ void k_copy4(const float4* __restrict__ src, float4* __restrict__ dst,
                        const int* __restrict__ tiers, long n4) {
    long i = (long)blockIdx.x * blockDim.x + threadIdx.x;
    if (i >= n4) return;
    int row = (int)(i >> 6);
    if (tiers[row] != 1) dst[i] = src[i];
}

__global__ __launch_bounds__(256) void k_qnorm(const float* __restrict__ q, int D) {
    int b = blockIdx.x, t = threadIdx.x;
    float ss = 0.f;
    for (int c = t; c < D; c += 256) { float v = q[(size_t)b * D + c]; ss += v * v; }
    __shared__ float red[256];
    red[t] = ss; __syncthreads();
    for (int s = 128; s > 0; s >>= 1) { if (t < s) red[t] += red[t + s]; __syncthreads(); }
    float scale = 1.f / (sqrtf(red[0]) + 1e-10f);
    for (int c = t; c < D; c += 256) g_qn[(size_t)b * D + c] = q[(size_t)b * D + c] * scale;
}

__global__ void k_klfin(float* klout, int W) {
    int n = g_nwarm > 0 ? g_nwarm : 1;
    *klout = (float)(g_kl_sum / ((double)n * (double)W));
}

// ---------------- fused VAE encoder (HMMA + ldmatrix) ----------------------
// One block: 128 warm rows x 256 outputs (cols 0-127 mu, 128-255 lv), K=256.
// 3-pass hi/lo split. Epilogue: mu -> split bf16 store + KL(mu); lv -> KL(lv).
__global__ __launch_bounds__(512)
void k_vae(const float* __restrict__ feats,
           const float* __restrict__ b_mu, const float* __restrict__ b_lv) {
    extern __shared__ char smem[];
    const int M = g_nwarm;
    const int m0 = blockIdx.x * 128;
    if (m0 >= M) return;

    const int tid = threadIdx.x, wid = tid >> 5, lane = tid & 31;
    const int wm = wid >> 2, wn = wid & 3;  // warp tile: 32 rows x 64 cols
    const uint32_t sb = smem_u32(smem);

    float acc[2][8][4];
    #pragma unroll
    for (int mi = 0; mi < 2; mi++)
        #pragma unroll
        for (int ni = 0; ni < 8; ni++)
            #pragma unroll
            for (int j = 0; j < 4; j++) acc[mi][ni][j] = 0.f;

    // ldmatrix per-lane address components
    const int aRow = (lane & 15), aColSel = (lane >> 4) << 3;          // A: row r+aRow, col kk+aColSel
    const int bRow = (lane & 7) + ((lane & 16) >> 1), bColSel = lane & 8;  // B pair

    for (int c = 0; c < 4; c++) {
        const int k0 = c * 64;
        // stage A: 128 warm rows x 64 cols fp32 -> split bf16
        #pragma unroll
        for (int it = 0; it < 4; it++) {
            int id = tid + it * 512;
            int m = id >> 4, kq = id & 15;
            int r = m0 + m;
            int arow = g_warm_idx[(r < M) ? r : m0];
            float4 v = *(const float4*)(feats + (size_t)arow * 256 + k0 + kq * 4);
            split_store4(smem, m, kq * 4, v, OFF_AH, OFF_AL);
        }
        // stage B: copy pre-converted weights, 256 rows x 64 cols (hi + lo)
        #pragma unroll
        for (int it = 0; it < 4; it++) {
            int id = tid + it * 512;
            int n = id >> 3, q = id & 7;
            size_t src = (size_t)n * 256 + k0 + q * 8;
            size_t dst = ((size_t)n * TSTRIDE + q * 8) * 2;
            *(uint4*)(smem + OFF_BH + dst) = *(const uint4*)(g_Wh + src);
            *(uint4*)(smem + OFF_BL + dst) = *(const uint4*)(g_Wl + src);
        }
        __syncthreads();

        #pragma unroll
        for (int kk = 0; kk < 64; kk += 16) {
            uint32_t ah[2][4], al[2][4];
            #pragma unroll
            for (int mi = 0; mi < 2; mi++) {
                uint32_t off = ((uint32_t)(wm * 32 + mi * 16 + aRow) * TSTRIDE + kk + aColSel) * 2;
                ldm4(sb + OFF_AH + off, ah[mi]);
                ldm4(sb + OFF_AL + off, al[mi]);
            }
            #pragma unroll
            for (int np = 0; np < 4; np++) {
                int n0 = wn * 64 + np * 16;
                uint32_t boff = ((uint32_t)(n0 + bRow) * TSTRIDE + kk + bColSel) * 2;
                uint32_t bh[4], bl[4];
                ldm4(sb + OFF_BH + boff, bh);
                ldm4(sb + OFF_BL + boff, bl);
                #pragma unroll
                for (int mi = 0; mi < 2; mi++) {
                    MMA16816(acc[mi][np * 2],     ah[mi], &bh[0]);
                    MMA16816(acc[mi][np * 2],     al[mi], &bh[0]);
                    MMA16816(acc[mi][np * 2],     ah[mi], &bl[0]);
                    MMA16816(acc[mi][np * 2 + 1], ah[mi], &bh[2]);
                    MMA16816(acc[mi][np * 2 + 1], al[mi], &bh[2]);
                    MMA16816(acc[mi][np * 2 + 1], ah[mi], &bl[2]);
                }
            }
        }
        __syncthreads();
    }

    // epilogue
    const int gq = lane >> 2, qq = (lane & 3) * 2;
    float kl = 0.f;
    #pragma unroll
    for (int mi = 0; mi < 2; mi++) {
        #pragma unroll
        for (int half = 0; half < 2; half++) {
            int grow = m0 + wm * 32 + mi * 16 + gq + half * 8;
            if (grow >= M) continue;
            #pragma unroll
            for (int ni = 0; ni < 8; ni++) {
                int col = wn * 64 + ni * 8 + qq;
                int is_lv = col >> 7;  // cols 128-255 = lv
                int cl = col & 127;
                float bias0 = is_lv ? b_lv[cl] : b_mu[cl];
                float bias1 = is_lv ? b_lv[cl + 1] : b_mu[cl + 1];
                float v0 = acc[mi][ni][half * 2 + 0] + bias0;
                float v1 = acc[mi][ni][half * 2 + 1] + bias1;
                if (!is_lv) {
                    __nv_bfloat16 h0 = __float2bfloat16(v0), h1 = __float2bfloat16(v1);
                    float l0 = v0 - __bfloat162float(h0), l1 = v1 - __bfloat162float(h1);
                    size_t o = (size_t)grow * 128 + cl;
                    *(uint32_t*)(g_muh + o) = pk2(h0, h1);
                    *(uint32_t*)(g_mul + o) = pk2(__float2bfloat16(l0), __float2bfloat16(l1));
                    kl += 0.5f * (v0 * v0 + v1 * v1) - 1.0f;
                } else {
                    kl += 0.5f * (expf(v0) + expf(v1)) - 0.5f * (v0 + v1);
                }
            }
        }
    }
    #pragma unroll
    for (int o = 16; o > 0; o >>= 1) kl += __shfl_xor_sync(0xffffffffu, kl, o);
    if (lane == 0 && kl != 0.f) atomicAdd(&g_kl_sum, (double)kl);
}

// ---------------- decoder (HMMA + ldmatrix): dec = mu @ W_dec^T + b_dec ----
// One block: 128 warm rows x 256 cols, K=128. A already split bf16.
__global__ __launch_bounds__(512)
void k_dec(const float* __restrict__ b_dec, float* __restrict__ newf) {
    extern __shared__ char smem[];
    const int M = g_nwarm;
    const int m0 = blockIdx.x * 128;
    if (m0 >= M) return;

    const int tid = threadIdx.x, wid = tid >> 5, lane = tid & 31;
    const int wm = wid >> 2, wn = wid & 3;
    const uint32_t sb = smem_u32(smem);

    float acc[2][8][4];
    #pragma unroll
    for (int mi = 0; mi < 2; mi++)
        #pragma unroll
        for (int ni = 0; ni < 8; ni++)
            #pragma unroll
            for (int j = 0; j < 4; j++) acc[mi][ni][j] = 0.f;

    const int aRow = (lane & 15), aColSel = (lane >> 4) << 3;
    const int bRow = (lane & 7) + ((lane & 16) >> 1), bColSel = lane & 8;

    for (int c = 0; c < 2; c++) {
        const int k0 = c * 64;
        // stage A: copy split-bf16 mu, 128 rows x 64 cols
        #pragma unroll
        for (int it = 0; it < 2; it++) {
            int id = tid + it * 512;
            int m = id >> 3, q = id & 7;
            int r = m0 + m;
            size_t src = (size_t)((r < M) ? r : m0) * 128 + k0 + q * 8;
            size_t dst = ((size_t)m * TSTRIDE + q * 8) * 2;
            *(uint4*)(smem + OFF_AH + dst) = *(const uint4*)(g_muh + src);
            *(uint4*)(smem + OFF_AL + dst) = *(const uint4*)(g_mul + src);
        }
        // stage B: copy pre-converted W_dec, 256 rows x 64 cols
        #pragma unroll
        for (int it = 0; it < 4; it++) {
            int id = tid + it * 512;
            int n = id >> 3, q = id & 7;
            size_t src = (size_t)n * 128 + k0 + q * 8;
            size_t dst = ((size_t)n * TSTRIDE + q * 8) * 2;
            *(uint4*)(smem + OFF_BH + dst) = *(const uint4*)(g_Dh + src);
            *(uint4*)(smem + OFF_BL + dst) = *(const uint4*)(g_Dl + src);
        }
        __syncthreads();

        #pragma unroll
        for (int kk = 0; kk < 64; kk += 16) {
            uint32_t ah[2][4], al[2][4];
            #pragma unroll
            for (int mi = 0; mi < 2; mi++) {
                uint32_t off = ((uint32_t)(wm * 32 + mi * 16 + aRow) * TSTRIDE + kk + aColSel) * 2;
                ldm4(sb + OFF_AH + off, ah[mi]);
                ldm4(sb + OFF_AL + off, al[mi]);
            }
            #pragma unroll
            for (int np = 0; np < 4; np++) {
                int n0 = wn * 64 + np * 16;
                uint32_t boff = ((uint32_t)(n0 + bRow) * TSTRIDE + kk + bColSel) * 2;
                uint32_t bh[4], bl[4];
                ldm4(sb + OFF_BH + boff, bh);
                ldm4(sb + OFF_BL + boff, bl);
                #pragma unroll
                for (int mi = 0; mi < 2; mi++) {
                    MMA16816(acc[mi][np * 2],     ah[mi], &bh[0]);
                    MMA16816(acc[mi][np * 2],     al[mi], &bh[0]);
                    MMA16816(acc[mi][np * 2],     ah[mi], &bl[0]);
                    MMA16816(acc[mi][np * 2 + 1], ah[mi], &bh[2]);
                    MMA16816(acc[mi][np * 2 + 1], al[mi], &bh[2]);
                    MMA16816(acc[mi][np * 2 + 1], ah[mi], &bl[2]);
                }
            }
        }
        __syncthreads();
    }

    // epilogue: scatter to warm rows of new_features
    const int gq = lane >> 2, qq = (lane & 3) * 2;
    #pragma unroll
    for (int mi = 0; mi < 2; mi++) {
        #pragma unroll
        for (int half = 0; half < 2; half++) {
            int grow = m0 + wm * 32 + mi * 16 + gq + half * 8;
            if (grow >= M) continue;
            int wr = g_warm_idx[grow];
            #pragma unroll
            for (int ni = 0; ni < 8; ni++) {
                int col = wn * 64 + ni * 8 + qq;
                float2 v = make_float2(acc[mi][ni][half * 2 + 0] + b_dec[col],
                                       acc[mi][ni][half * 2 + 1] + b_dec[col + 1]);
                *(float2*)(newf + (size_t)wr * 256 + col) = v;
            }
        }
    }
}

// ---------------- sim GEMM (fp32 SIMT; fused row norms) -------------------
__global__ __launch_bounds__(256) void k_sim(const float* __restrict__ feats, int D, int simld) {
    const int M = g_ncold;
    const int m0 = blockIdx.x * 128;
    if (m0 >= M) return;

    __shared__ float Xs[16][128];
    __shared__ float Qs[16][64];

    const int tid = threadIdx.x;
    const int ty = tid >> 4, tx = tid & 15;

    float acc[8][4];
    float ssq[8];
    #pragma unroll
    for (int i = 0; i < 8; i++) {
        ssq[i] = 0.f;
        #pragma unroll
        for (int j = 0; j < 4; j++) acc[i][j] = 0.f;
    }

    for (int k0 = 0; k0 < D; k0 += 16) {
        #pragma unroll
        for (int i = 0; i < 2; i++) {
            int id = tid + i * 256;
            int m = id & 127, kq = id >> 7;
            int r = m0 + m;
            int arow = (r < M) ? g_cold_idx[r] : g_cold_idx[m0];
            float4 v = *(const float4*)(feats + (size_t)arow * D + k0 + kq * 4);
            Xs[kq * 4 + 0][m] = v.x; Xs[kq * 4 + 1][m] = v.y;
            Xs[kq * 4 + 2][m] = v.z; Xs[kq * 4 + 3][m] = v.w;
        }
        {
            int q = tid & 63, kq = tid >> 6;
            float4 v = *(const float4*)(g_qn + (size_t)q * D + k0 + kq * 4);
            Qs[kq * 4 + 0][q] = v.x; Qs[kq * 4 + 1][q] = v.y;
            Qs[kq * 4 + 2][q] = v.z; Qs[kq * 4 + 3][q] = v.w;
        }
        __syncthreads();
        #pragma unroll
        for (int kk = 0; kk < 16; kk++) {
            float4 a0 = *(const float4*)&Xs[kk][ty * 4];
            float4 a1 = *(const float4*)&Xs[kk][ty * 4 + 64];
            float4 b0 = *(const float4*)&Qs[kk][tx * 4];
            float a[8] = {a0.x, a0.y, a0.z, a0.w, a1.x, a1.y, a1.z, a1.w};
            float b[4] = {b0.x, b0.y, b0.z, b0.w};
            #pragma unroll
            for (int i = 0; i < 8; i++) {
                ssq[i] += a[i] * a[i];
                #pragma unroll
                for (int j = 0; j < 4; j++) acc[i][j] += a[i] * b[j];
            }
        }
        __syncthreads();
    }

    #pragma unroll
    for (int i = 0; i < 8; i++) {
        int rl = (i < 4) ? (ty * 4 + i) : (64 + ty * 4 + i - 4);
        int j = m0 + rl;
        if (j < M) {
            float inv = 1.f / (sqrtf(ssq[i]) + 1e-10f);
            #pragma unroll
            for (int jj = 0; jj < 4; jj++) {
                int q = tx * 4 + jj;
                g_sim[(size_t)q * simld + j] = acc[i][jj] * inv;
            }
        }
    }
}

// ---------------- top-k (value desc, index asc tie-break) ------------------
__global__ __launch_bounds__(256) void k_topk(int simld, int k, float* __restrict__ out_idx_f) {
    const int b = blockIdx.x;
    const int ncold = g_ncold;
    const int t = threadIdx.x;

    float lv[16]; int li[16];
    #pragma unroll
    for (int s = 0; s < 16; s++) { lv[s] = -INFINITY; li[s] = 0x7fffffff; }

    const float* srow = g_sim + (size_t)b * simld;
    for (int j = t; j < ncold; j += 256) {
        float v = srow[j];
        int gi = g_cold_idx[j];
        if (v > lv[0] || (v == lv[0] && gi < li[0])) {
            lv[0] = v; li[0] = gi;
            #pragma unroll
            for (int s = 0; s < 15; s++) {
                bool sw = (lv[s] > lv[s + 1]) || (lv[s] == lv[s + 1] && li[s] < li[s + 1]);
                if (sw) {
                    float tv = lv[s]; lv[s] = lv[s + 1]; lv[s + 1] = tv;
                    int ti = li[s]; li[s] = li[s + 1]; li[s + 1] = ti;
                }
            }
        }
    }

    __shared__ float sval[4096];
    __shared__ int   sidxs[4096];
    __shared__ float rv[256];
    __shared__ int   ri[256];
    __shared__ int   rp[256];

    #pragma unroll
    for (int s = 0; s < 16; s++) { sval[t * 16 + s] = lv[s]; sidxs[t * 16 + s] = li[s]; }
    __syncthreads();

    for (int sel = 0; sel < k; sel++) {
        float bv = -INFINITY; int bi = 0x7fffffff; int bp = -1;
        for (int p = t; p < 4096; p += 256) {
            float v = sval[p]; int gi = sidxs[p];
            if (v > bv || (v == bv && gi < bi)) { bv = v; bi = gi; bp = p; }
        }
        rv[t] = bv; ri[t] = bi; rp[t] = bp;
        __syncthreads();
        for (int s = 128; s > 0; s >>= 1) {
            if (t < s) {
                if (rv[t + s] > rv[t] || (rv[t + s] == rv[t] && ri[t + s] < ri[t])) {
                    rv[t] = rv[t + s]; ri[t] = ri[t + s]; rp[t] = rp[t + s];
                }
            }
            __syncthreads();
        }
        if (t == 0) {
            g_topidx[b * 32 + sel] = ri[0];
            out_idx_f[(size_t)b * k + sel] = (float)ri[0];
            if (rp[0] >= 0) { sval[rp[0]] = -INFINITY; sidxs[rp[0]] = 0x7fffffff; }
        }
        __syncthreads();
    }
}

// Scalar stores: ret base is d_out + N*D + 1 floats (only 4B aligned).
__global__ __launch_bounds__(256) void k_gather(const float* __restrict__ newf,
                                                float* __restrict__ ret, int D, int k) {
    int r = blockIdx.x;
    int row = g_topidx[(r / k) * 32 + (r % k)];
    const float* s = newf + (size_t)row * D;
    float* d = ret + (size_t)r * D;
    for (int c = threadIdx.x; c < D; c += blockDim.x) d[c] = s[c];
}

extern "C" void kernel_launch(void* const* d_in, const int* in_sizes, int n_in,
                              void* d_out, int out_size) {
    const float* feats = (const float*)d_in[0];
    const int*   tiers = (const int*)d_in[1];
    const float* query = (const float*)d_in[2];
    const float* W_mu  = (const float*)d_in[3];
    const float* b_mu  = (const float*)d_in[4];
    const float* W_lv  = (const float*)d_in[5];
    const float* b_lv  = (const float*)d_in[6];
    const float* W_dec = (const float*)d_in[7];
    const float* b_dec = (const float*)d_in[8];

    const int N = in_sizes[1];
    const int D = in_sizes[0] / N;
    const int B = in_sizes[2] / D;
    const int W = in_sizes[4];
    const long k = ((long)out_size - (long)N * D - 1) / ((long)B * (D + 1));

    float* out   = (float*)d_out;
    float* newf  = out;
    float* klp   = out + (size_t)N * D;
    float* ret   = klp + 1;
    float* tidxf = ret + (size_t)B * k * D;

    cudaFuncSetAttribute(k_vae, cudaFuncAttributeMaxDynamicSharedMemorySize, DSMEM_SZ);
    cudaFuncSetAttribute(k_dec, cudaFuncAttributeMaxDynamicSharedMemorySize, DSMEM_SZ);

    k_init<<<1, 1>>>();
    k_partition<<<(N + 255) / 256, 256>>>(tiers, N);
    k_wprep<<<384, 256>>>(W_mu, W_lv, W_dec);
    k_qnorm<<<B, 256>>>(query, D);

    long n4 = (long)N * D / 4;
    k_copy4<<<(unsigned)((n4 + 255) / 256), 256>>>((const float4*)feats, (float4*)newf, tiers, n4);

    const int gy = (N + 127) / 128;
    k_vae<<<gy, 512, DSMEM_SZ>>>(feats, b_mu, b_lv);
    k_klfin<<<1, 1>>>(klp, W);
    k_dec<<<gy, 512, DSMEM_SZ>>>(b_dec, newf);

    k_sim<<<gy, 256>>>(feats, D, N);
    k_topk<<<B, 256>>>(N, (int)k, tidxf);
    k_gather<<<B * (int)k, 256>>>(newf, ret, D, (int)k);
}

// round 7
// speedup vs baseline: 1.5094x; 1.0235x over previous
#include <cuda_runtime.h>
#include <cuda_bf16.h>
#include <math.h>
#include <stdint.h>

// ---------------- static scratch (no allocations allowed) ----------------
#define MAXN 204800
#define MAXB 64

__device__ int    g_warm_idx[MAXN];
__device__ int    g_cold_idx[MAXN];
__device__ int    g_nwarm;
__device__ int    g_ncold;
__device__ double g_kl_sum;
__device__ float  g_sim[(size_t)MAXB * MAXN];
__device__ float  g_qn[MAXB * 256];
__device__ int    g_topidx[MAXB * 32];
// pre-converted weights (hi/lo split), [n][k] row-major
__device__ __nv_bfloat16 g_Wh[256 * 256];  // rows 0-127 = W_mu, 128-255 = W_lv
__device__ __nv_bfloat16 g_Wl[256 * 256];
__device__ __nv_bfloat16 g_Dh[256 * 128];  // W_dec
__device__ __nv_bfloat16 g_Dl[256 * 128];

// ---------------- helpers ----------------
__device__ __forceinline__ uint32_t pk2(__nv_bfloat16 a, __nv_bfloat16 b) {
    return (uint32_t)__bfloat16_as_ushort(a) | ((uint32_t)__bfloat16_as_ushort(b) << 16);
}
__device__ __forceinline__ uint32_t smem_u32(const void* p) {
    uint32_t a;
    asm("{ .reg .u64 t; cvta.to.shared.u64 t, %1; cvt.u32.u64 %0, t; }" : "=r"(a) : "l"(p));
    return a;
}

#define MMA16816(c, a, b) asm volatile( \
    "mma.sync.aligned.m16n8k16.row.col.f32.bf16.bf16.f32 " \
    "{%0,%1,%2,%3}, {%4,%5,%6,%7}, {%8,%9}, {%0,%1,%2,%3};" \
    : "+f"((c)[0]), "+f"((c)[1]), "+f"((c)[2]), "+f"((c)[3]) \
    : "r"((a)[0]), "r"((a)[1]), "r"((a)[2]), "r"((a)[3]), "r"((b)[0]), "r"((b)[1]))

__device__ __forceinline__ void ldm4(uint32_t addr, uint32_t r[4]) {
    asm volatile("ldmatrix.sync.aligned.m8n8.x4.shared.b16 {%0,%1,%2,%3}, [%4];"
                 : "=r"(r[0]), "=r"(r[1]), "=r"(r[2]), "=r"(r[3]) : "r"(addr));
}

// smem layout for k_warm (bytes)
#define TSTRIDE 72           // A/B tile stride in bf16
#define MUSTRIDE 136         // mu tile stride in bf16 (128 cols + pad)
#define OFF_AH  0
#define OFF_AL  18432
#define OFF_BH  36864
#define OFF_BL  73728
#define OFF_MUH 110592
#define OFF_MUL 145408
#define DSMEM_SZ 180224

// split fp32x4 -> bf16 hi/lo, store 8B each into [m][k..k+3]
__device__ __forceinline__ void split_store4(char* smem, int m, int k, float4 v,
                                             int off_hi, int off_lo) {
    __nv_bfloat16 h0 = __float2bfloat16(v.x), h1 = __float2bfloat16(v.y);
    __nv_bfloat16 h2 = __float2bfloat16(v.z), h3 = __float2bfloat16(v.w);
    float l0 = v.x - __bfloat162float(h0), l1 = v.y - __bfloat162float(h1);
    float l2 = v.z - __bfloat162float(h2), l3 = v.w - __bfloat162float(h3);
    size_t base = (size_t)m * TSTRIDE + k;
    *(uint2*)(smem + off_hi + base * 2) = make_uint2(pk2(h0, h1), pk2(h2, h3));
    *(uint2*)(smem + off_lo + base * 2) =
        make_uint2(pk2(__float2bfloat16(l0), __float2bfloat16(l1)),
                   pk2(__float2bfloat16(l2), __float2bfloat16(l3)));
}

// ---------------- small kernels ----------------
__global__ void k_init() { g_nwarm = 0; g_ncold = 0; g_kl_sum = 0.0; }

__global__ void k_partition(const int* __restrict__ tiers, int N) {
    int i = blockIdx.x * blockDim.x + threadIdx.x;
    if (i >= N) return;
    int t = tiers[i];
    if (t == 1)      g_warm_idx[atomicAdd(&g_nwarm, 1)] = i;
    else if (t == 2) g_cold_idx[atomicAdd(&g_ncold, 1)] = i;
}

// pre-convert weights to split bf16 (once per launch)
__global__ __launch_bounds__(256) void k_wprep(const float* __restrict__ W_mu,
                                               const float* __restrict__ W_lv,
                                               const float* __restrict__ W_dec) {
    int idx = blockIdx.x * blockDim.x + threadIdx.x;
    if (idx < 65536) {
        int n = idx >> 8, k = idx & 255;
        float w = (n < 128) ? W_mu[(size_t)n * 256 + k] : W_lv[(size_t)(n - 128) * 256 + k];
        __nv_bfloat16 h = __float2bfloat16(w);
        g_Wh[idx] = h;
        g_Wl[idx] = __float2bfloat16(w - __bfloat162float(h));
    } else if (idx < 65536 + 32768) {
        int j = idx - 65536;
        float w = W_dec[j];
        __nv_bfloat16 h = __float2bfloat16(w);
        g_Dh[j] = h;
        g_Dl[j] = __float2bfloat16(w - __bfloat162float(h));
    }
}

// copy new_features = node_features, skipping warm rows (k_warm writes them)
__global__ void k_copy4(const float4* __restrict__ src, float4* __restrict__ dst,
                        const int* __restrict__ tiers, long n4) {
    long i = (long)blockIdx.x * blockDim.x + threadIdx.x;
    if (i >= n4) return;
    int row = (int)(i >> 6);
    if (tiers[row] != 1) dst[i] = src[i];
}

__global__ __launch_bounds__(256) void k_qnorm(const float* __restrict__ q, int D) {
    int b = blockIdx.x, t = threadIdx.x;
    float ss = 0.f;
    for (int c = t; c < D; c += 256) { float v = q[(size_t)b * D + c]; ss += v * v; }
    __shared__ float red[256];
    red[t] = ss; __syncthreads();
    for (int s = 128; s > 0; s >>= 1) { if (t < s) red[t] += red[t + s]; __syncthreads(); }
    float scale = 1.f / (sqrtf(red[0]) + 1e-10f);
    for (int c = t; c < D; c += 256) g_qn[(size_t)b * D + c] = q[(size_t)b * D + c] * scale;
}

__global__ void k_klfin(float* klout, int W) {
    int n = g_nwarm > 0 ? g_nwarm : 1;
    *klout = (float)(g_kl_sum / ((double)n * (double)W));
}

// ---------------- fused warm pipeline: [mu|lv] GEMM + KL + decoder ---------
// Phase 1: [mu|lv](128x256) = X_warm(128x256) @ [Wmu;Wlv]^T, 3-pass hi/lo.
//          Epilogue: KL both parts; mu -> split bf16 into SMEM (no DRAM trip).
// Phase 2: dec(128x256) = mu(128x128) @ Wdec^T, A-frags ldmatrix'd straight
//          from the SMEM mu tiles; scatter rows to new_features[warm].
__global__ __launch_bounds__(512)
void k_warm(const float* __restrict__ feats,
            const float* __restrict__ b_mu, const float* __restrict__ b_lv,
            const float* __restrict__ b_dec, float* __restrict__ newf) {
    extern __shared__ char smem[];
    const int M = g_nwarm;
    const int m0 = blockIdx.x * 128;
    if (m0 >= M) return;

    const int tid = threadIdx.x, wid = tid >> 5, lane = tid & 31;
    const int wm = wid >> 2, wn = wid & 3;  // warp tile: 32 rows x 64 cols
    const uint32_t sb = smem_u32(smem);

    float acc[2][8][4];
    #pragma unroll
    for (int mi = 0; mi < 2; mi++)
        #pragma unroll
        for (int ni = 0; ni < 8; ni++)
            #pragma unroll
            for (int j = 0; j < 4; j++) acc[mi][ni][j] = 0.f;

    const int aRow = (lane & 15), aColSel = (lane >> 4) << 3;
    const int bRow = (lane & 7) + ((lane & 16) >> 1), bColSel = lane & 8;
    const int gq = lane >> 2, qq = (lane & 3) * 2;

    // ===== phase 1: [mu|lv] =====
    for (int c = 0; c < 4; c++) {
        const int k0 = c * 64;
        #pragma unroll
        for (int it = 0; it < 4; it++) {
            int id = tid + it * 512;
            int m = id >> 4, kq = id & 15;
            int r = m0 + m;
            int arow = g_warm_idx[(r < M) ? r : m0];
            float4 v = *(const float4*)(feats + (size_t)arow * 256 + k0 + kq * 4);
            split_store4(smem, m, kq * 4, v, OFF_AH, OFF_AL);
        }
        #pragma unroll
        for (int it = 0; it < 4; it++) {
            int id = tid + it * 512;
            int n = id >> 3, q = id & 7;
            size_t src = (size_t)n * 256 + k0 + q * 8;
            size_t dst = ((size_t)n * TSTRIDE + q * 8) * 2;
            *(uint4*)(smem + OFF_BH + dst) = *(const uint4*)(g_Wh + src);
            *(uint4*)(smem + OFF_BL + dst) = *(const uint4*)(g_Wl + src);
        }
        __syncthreads();

        #pragma unroll
        for (int kk = 0; kk < 64; kk += 16) {
            uint32_t ah[2][4], al[2][4];
            #pragma unroll
            for (int mi = 0; mi < 2; mi++) {
                uint32_t off = ((uint32_t)(wm * 32 + mi * 16 + aRow) * TSTRIDE + kk + aColSel) * 2;
                ldm4(sb + OFF_AH + off, ah[mi]);
                ldm4(sb + OFF_AL + off, al[mi]);
            }
            #pragma unroll
            for (int np = 0; np < 4; np++) {
                int n0 = wn * 64 + np * 16;
                uint32_t boff = ((uint32_t)(n0 + bRow) * TSTRIDE + kk + bColSel) * 2;
                uint32_t bh[4], bl[4];
                ldm4(sb + OFF_BH + boff, bh);
                ldm4(sb + OFF_BL + boff, bl);
                #pragma unroll
                for (int mi = 0; mi < 2; mi++) {
                    MMA16816(acc[mi][np * 2],     ah[mi], &bh[0]);
                    MMA16816(acc[mi][np * 2],     al[mi], &bh[0]);
                    MMA16816(acc[mi][np * 2],     ah[mi], &bl[0]);
                    MMA16816(acc[mi][np * 2 + 1], ah[mi], &bh[2]);
                    MMA16816(acc[mi][np * 2 + 1], al[mi], &bh[2]);
                    MMA16816(acc[mi][np * 2 + 1], ah[mi], &bl[2]);
                }
            }
        }
        __syncthreads();
    }

    // ===== epilogue 1: KL + mu -> smem (split bf16) =====
    float kl = 0.f;
    #pragma unroll
    for (int mi = 0; mi < 2; mi++) {
        #pragma unroll
        for (int half = 0; half < 2; half++) {
            int rl = wm * 32 + mi * 16 + gq + half * 8;
            int grow = m0 + rl;
            bool valid = grow < M;
            #pragma unroll
            for (int ni = 0; ni < 8; ni++) {
                int col = wn * 64 + ni * 8 + qq;
                int is_lv = col >> 7;
                int cl = col & 127;
                float bias0 = is_lv ? b_lv[cl] : b_mu[cl];
                float bias1 = is_lv ? b_lv[cl + 1] : b_mu[cl + 1];
                float v0 = acc[mi][ni][half * 2 + 0] + bias0;
                float v1 = acc[mi][ni][half * 2 + 1] + bias1;
                if (!is_lv) {
                    __nv_bfloat16 h0 = __float2bfloat16(v0), h1 = __float2bfloat16(v1);
                    float l0 = v0 - __bfloat162float(h0), l1 = v1 - __bfloat162float(h1);
                    uint32_t o = ((uint32_t)rl * MUSTRIDE + cl) * 2;
                    *(uint32_t*)(smem + OFF_MUH + o) = pk2(h0, h1);
                    *(uint32_t*)(smem + OFF_MUL + o) = pk2(__float2bfloat16(l0), __float2bfloat16(l1));
                    if (valid) kl += 0.5f * (v0 * v0 + v1 * v1) - 1.0f;
                } else if (valid) {
                    kl += 0.5f * (expf(v0) + expf(v1)) - 0.5f * (v0 + v1);
                }
            }
        }
    }
    #pragma unroll
    for (int o = 16; o > 0; o >>= 1) kl += __shfl_xor_sync(0xffffffffu, kl, o);
    if (lane == 0 && kl != 0.f) atomicAdd(&g_kl_sum, (double)kl);
    __syncthreads();

    // ===== phase 2: dec = mu @ Wdec^T =====
    #pragma unroll
    for (int mi = 0; mi < 2; mi++)
        #pragma unroll
        for (int ni = 0; ni < 8; ni++)
            #pragma unroll
            for (int j = 0; j < 4; j++) acc[mi][ni][j] = 0.f;

    for (int c = 0; c < 2; c++) {
        const int k0 = c * 64;
        // stage B: pre-converted Wdec, 256 rows x 64 cols
        #pragma unroll
        for (int it = 0; it < 4; it++) {
            int id = tid + it * 512;
            int n = id >> 3, q = id & 7;
            size_t src = (size_t)n * 128 + k0 + q * 8;
            size_t dst = ((size_t)n * TSTRIDE + q * 8) * 2;
            *(uint4*)(smem + OFF_BH + dst) = *(const uint4*)(g_Dh + src);
            *(uint4*)(smem + OFF_BL + dst) = *(const uint4*)(g_Dl + src);
        }
        __syncthreads();

        #pragma unroll
        for (int kk = 0; kk < 64; kk += 16) {
            uint32_t ah[2][4], al[2][4];
            #pragma unroll
            for (int mi = 0; mi < 2; mi++) {
                uint32_t off = ((uint32_t)(wm * 32 + mi * 16 + aRow) * MUSTRIDE + k0 + kk + aColSel) * 2;
                ldm4(sb + OFF_MUH + off, ah[mi]);
                ldm4(sb + OFF_MUL + off, al[mi]);
            }
            #pragma unroll
            for (int np = 0; np < 4; np++) {
                int n0 = wn * 64 + np * 16;
                uint32_t boff = ((uint32_t)(n0 + bRow) * TSTRIDE + kk + bColSel) * 2;
                uint32_t bh[4], bl[4];
                ldm4(sb + OFF_BH + boff, bh);
                ldm4(sb + OFF_BL + boff, bl);
                #pragma unroll
                for (int mi = 0; mi < 2; mi++) {
                    MMA16816(acc[mi][np * 2],     ah[mi], &bh[0]);
                    MMA16816(acc[mi][np * 2],     al[mi], &bh[0]);
                    MMA16816(acc[mi][np * 2],     ah[mi], &bl[0]);
                    MMA16816(acc[mi][np * 2 + 1], ah[mi], &bh[2]);
                    MMA16816(acc[mi][np * 2 + 1], al[mi], &bh[2]);
                    MMA16816(acc[mi][np * 2 + 1], ah[mi], &bl[2]);
                }
            }
        }
        __syncthreads();
    }

    // ===== epilogue 2: scatter dec to warm rows =====
    #pragma unroll
    for (int mi = 0; mi < 2; mi++) {
        #pragma unroll
        for (int half = 0; half < 2; half++) {
            int grow = m0 + wm * 32 + mi * 16 + gq + half * 8;
            if (grow >= M) continue;
            int wr = g_warm_idx[grow];
            #pragma unroll
            for (int ni = 0; ni < 8; ni++) {
                int col = wn * 64 + ni * 8 + qq;
                float2 v = make_float2(acc[mi][ni][half * 2 + 0] + b_dec[col],
                                       acc[mi][ni][half * 2 + 1] + b_dec[col + 1]);
                *(float2*)(newf + (size_t)wr * 256 + col) = v;
            }
        }
    }
}

// ---------------- sim GEMM (fp32 SIMT; fused row norms) -------------------
__global__ __launch_bounds__(256) void k_sim(const float* __restrict__ feats, int D, int simld) {
    const int M = g_ncold;
    const int m0 = blockIdx.x * 128;
    if (m0 >= M) return;

    __shared__ float Xs[16][128];
    __shared__ float Qs[16][64];

    const int tid = threadIdx.x;
    const int ty = tid >> 4, tx = tid & 15;

    float acc[8][4];
    float ssq[8];
    #pragma unroll
    for (int i = 0; i < 8; i++) {
        ssq[i] = 0.f;
        #pragma unroll
        for (int j = 0; j < 4; j++) acc[i][j] = 0.f;
    }

    for (int k0 = 0; k0 < D; k0 += 16) {
        #pragma unroll
        for (int i = 0; i < 2; i++) {
            int id = tid + i * 256;
            int m = id & 127, kq = id >> 7;
            int r = m0 + m;
            int arow = (r < M) ? g_cold_idx[r] : g_cold_idx[m0];
            float4 v = *(const float4*)(feats + (size_t)arow * D + k0 + kq * 4);
            Xs[kq * 4 + 0][m] = v.x; Xs[kq * 4 + 1][m] = v.y;
            Xs[kq * 4 + 2][m] = v.z; Xs[kq * 4 + 3][m] = v.w;
        }
        {
            int q = tid & 63, kq = tid >> 6;
            float4 v = *(const float4*)(g_qn + (size_t)q * D + k0 + kq * 4);
            Qs[kq * 4 + 0][q] = v.x; Qs[kq * 4 + 1][q] = v.y;
            Qs[kq * 4 + 2][q] = v.z; Qs[kq * 4 + 3][q] = v.w;
        }
        __syncthreads();
        #pragma unroll
        for (int kk = 0; kk < 16; kk++) {
            float4 a0 = *(const float4*)&Xs[kk][ty * 4];
            float4 a1 = *(const float4*)&Xs[kk][ty * 4 + 64];
            float4 b0 = *(const float4*)&Qs[kk][tx * 4];
            float a[8] = {a0.x, a0.y, a0.z, a0.w, a1.x, a1.y, a1.z, a1.w};
            float b[4] = {b0.x, b0.y, b0.z, b0.w};
            #pragma unroll
            for (int i = 0; i < 8; i++) {
                ssq[i] += a[i] * a[i];
                #pragma unroll
                for (int j = 0; j < 4; j++) acc[i][j] += a[i] * b[j];
            }
        }
        __syncthreads();
    }

    #pragma unroll
    for (int i = 0; i < 8; i++) {
        int rl = (i < 4) ? (ty * 4 + i) : (64 + ty * 4 + i - 4);
        int j = m0 + rl;
        if (j < M) {
            float inv = 1.f / (sqrtf(ssq[i]) + 1e-10f);
            #pragma unroll
            for (int jj = 0; jj < 4; jj++) {
                int q = tx * 4 + jj;
                g_sim[(size_t)q * simld + j] = acc[i][jj] * inv;
            }
        }
    }
}

// ---------------- top-k (value desc, index asc tie-break) ------------------
__global__ __launch_bounds__(256) void k_topk(int simld, int k, float* __restrict__ out_idx_f) {
    const int b = blockIdx.x;
    const int ncold = g_ncold;
    const int t = threadIdx.x;

    float lv[16]; int li[16];
    #pragma unroll
    for (int s = 0; s < 16; s++) { lv[s] = -INFINITY; li[s] = 0x7fffffff; }

    const float* srow = g_sim + (size_t)b * simld;
    for (int j = t; j < ncold; j += 256) {
        float v = srow[j];
        int gi = g_cold_idx[j];
        if (v > lv[0] || (v == lv[0] && gi < li[0])) {
            lv[0] = v; li[0] = gi;
            #pragma unroll
            for (int s = 0; s < 15; s++) {
                bool sw = (lv[s] > lv[s + 1]) || (lv[s] == lv[s + 1] && li[s] < li[s + 1]);
                if (sw) {
                    float tv = lv[s]; lv[s] = lv[s + 1]; lv[s + 1] = tv;
                    int ti = li[s]; li[s] = li[s + 1]; li[s + 1] = ti;
                }
            }
        }
    }

    __shared__ float sval[4096];
    __shared__ int   sidxs[4096];
    __shared__ float rv[256];
    __shared__ int   ri[256];
    __shared__ int   rp[256];

    #pragma unroll
    for (int s = 0; s < 16; s++) { sval[t * 16 + s] = lv[s]; sidxs[t * 16 + s] = li[s]; }
    __syncthreads();

    for (int sel = 0; sel < k; sel++) {
        float bv = -INFINITY; int bi = 0x7fffffff; int bp = -1;
        for (int p = t; p < 4096; p += 256) {
            float v = sval[p]; int gi = sidxs[p];
            if (v > bv || (v == bv && gi < bi)) { bv = v; bi = gi; bp = p; }
        }
        rv[t] = bv; ri[t] = bi; rp[t] = bp;
        __syncthreads();
        for (int s = 128; s > 0; s >>= 1) {
            if (t < s) {
                if (rv[t + s] > rv[t] || (rv[t + s] == rv[t] && ri[t + s] < ri[t])) {
                    rv[t] = rv[t + s]; ri[t] = ri[t + s]; rp[t] = rp[t + s];
                }
            }
            __syncthreads();
        }
        if (t == 0) {
            g_topidx[b * 32 + sel] = ri[0];
            out_idx_f[(size_t)b * k + sel] = (float)ri[0];
            if (rp[0] >= 0) { sval[rp[0]] = -INFINITY; sidxs[rp[0]] = 0x7fffffff; }
        }
        __syncthreads();
    }
}

// Scalar stores: ret base is d_out + N*D + 1 floats (only 4B aligned).
__global__ __launch_bounds__(256) void k_gather(const float* __restrict__ newf,
                                                float* __restrict__ ret, int D, int k) {
    int r = blockIdx.x;
    int row = g_topidx[(r / k) * 32 + (r % k)];
    const float* s = newf + (size_t)row * D;
    float* d = ret + (size_t)r * D;
    for (int c = threadIdx.x; c < D; c += blockDim.x) d[c] = s[c];
}

extern "C" void kernel_launch(void* const* d_in, const int* in_sizes, int n_in,
                              void* d_out, int out_size) {
    const float* feats = (const float*)d_in[0];
    const int*   tiers = (const int*)d_in[1];
    const float* query = (const float*)d_in[2];
    const float* W_mu  = (const float*)d_in[3];
    const float* b_mu  = (const float*)d_in[4];
    const float* W_lv  = (const float*)d_in[5];
    const float* b_lv  = (const float*)d_in[6];
    const float* W_dec = (const float*)d_in[7];
    const float* b_dec = (const float*)d_in[8];

    const int N = in_sizes[1];
    const int D = in_sizes[0] / N;
    const int B = in_sizes[2] / D;
    const int W = in_sizes[4];
    const long k = ((long)out_size - (long)N * D - 1) / ((long)B * (D + 1));

    float* out   = (float*)d_out;
    float* newf  = out;
    float* klp   = out + (size_t)N * D;
    float* ret   = klp + 1;
    float* tidxf = ret + (size_t)B * k * D;

    cudaFuncSetAttribute(k_warm, cudaFuncAttributeMaxDynamicSharedMemorySize, DSMEM_SZ);

    const int gy = (N + 127) / 128;

    // order matters: ncu samples the 4th kernel launch -> k_warm this round
    k_init<<<1, 1>>>();
    k_partition<<<(N + 255) / 256, 256>>>(tiers, N);
    k_wprep<<<384, 256>>>(W_mu, W_lv, W_dec);
    k_warm<<<gy, 512, DSMEM_SZ>>>(feats, b_mu, b_lv, b_dec, newf);

    k_qnorm<<<B, 256>>>(query, D);
    long n4 = (long)N * D / 4;
    k_copy4<<<(unsigned)((n4 + 255) / 256), 256>>>((const float4*)feats, (float4*)newf, tiers, n4);

    k_sim<<<gy, 256>>>(feats, D, N);
    k_topk<<<B, 256>>>(N, (int)k, tidxf);
    k_gather<<<B * (int)k, 256>>>(newf, ret, D, (int)k);
    k_klfin<<<1, 1>>>(klp, W);
}